// round 10
// baseline (speedup 1.0000x reference)
#include <cuda_runtime.h>
#include <cuda.h>
#include <cuda_bf16.h>
#include <stdint.h>
#include <math.h>

// ================= problem constants =================
#define F_IN   45056
#define MROWS  4096          // 2048 batches x 2 perspectives
#define NOUT   256
#define KSPLIT 4
#define KTILE  64            // K elements per pipeline stage
#define NK_TOT (F_IN / KTILE)        // 704
#define NK_PER (NK_TOT / KSPLIT)     // 176
#define MTILE  128
#define NTILE  256

// ================= smem layout (nnue_l1) =================
#define SM_RAW  1024
#define SM_CVT  (SM_RAW + 2 * 32768)             // 66560
#define SM_BB   (SM_CVT + 2 * 16384)             // 99328
#define SMEM_SZ (SM_BB + 2 * 32768)              // 164864

#define MB_RAWF(i) (128 + (i) * 8)
#define MB_BF(i)   (160 + (i) * 8)

// ================= device scratch (no cudaMalloc allowed) =================
__device__ __align__(128) __nv_bfloat16 g_w1b[(size_t)NOUT * F_IN];     // 23 MB
__device__ __align__(128) float g_part[(size_t)KSPLIT * MROWS * NOUT];  // 16.8 MB

// ================= ptx helpers (baseline PTX only: sm_90-safe) =================
__device__ __forceinline__ uint32_t su32(const void* p) {
    uint32_t a;
    asm("{ .reg .u64 t; cvta.to.shared.u64 t, %1; cvt.u32.u64 %0, t; }" : "=r"(a) : "l"(p));
    return a;
}
__device__ __forceinline__ void mbi(uint32_t a, uint32_t c) {
    asm volatile("mbarrier.init.shared.b64 [%0], %1;" :: "r"(a), "r"(c) : "memory");
}
__device__ __forceinline__ void mbtx(uint32_t a, uint32_t b) {
    asm volatile("mbarrier.arrive.expect_tx.shared.b64 _, [%0], %1;" :: "r"(a), "r"(b) : "memory");
}
__device__ __forceinline__ void mbwait(uint32_t a, uint32_t p) {
    asm volatile(
        "{\n\t.reg .pred P;\n\t"
        "WL_%=:\n\t"
        "mbarrier.try_wait.parity.acquire.cta.shared::cta.b64 P, [%0], %1, 0x989680;\n\t"
        "@P bra WD_%=;\n\t"
        "bra WL_%=;\n\t"
        "WD_%=:\n\t}"
        :: "r"(a), "r"(p) : "memory");
}
__device__ __forceinline__ void tma2d(uint32_t dst, const void* map, int cx, int cy, uint32_t mb) {
    asm volatile(
        "cp.async.bulk.tensor.2d.shared::cta.global.tile.mbarrier::complete_tx::bytes "
        "[%0], [%1, {%2, %3}], [%4];"
        :: "r"(dst), "l"(map), "r"(cx), "r"(cy), "r"(mb) : "memory");
}
__device__ __forceinline__ void ldsm4(uint32_t* r, uint32_t addr) {
    asm volatile("ldmatrix.sync.aligned.m8n8.x4.shared.b16 {%0,%1,%2,%3}, [%4];"
        : "=r"(r[0]), "=r"(r[1]), "=r"(r[2]), "=r"(r[3]) : "r"(addr));
}
__device__ __forceinline__ void mma16816(float* c, const uint32_t* a, const uint32_t* b) {
    asm volatile(
        "mma.sync.aligned.m16n8k16.row.col.f32.bf16.bf16.f32 "
        "{%0,%1,%2,%3}, {%4,%5,%6,%7}, {%8,%9}, {%0,%1,%2,%3};"
        : "+f"(c[0]), "+f"(c[1]), "+f"(c[2]), "+f"(c[3])
        : "r"(a[0]), "r"(a[1]), "r"(a[2]), "r"(a[3]), "r"(b[0]), "r"(b[1]));
}
__device__ __forceinline__ uint32_t p2bf(float a, float b) {
    __nv_bfloat162 h = __floats2bfloat162_rn(a, b);
    return *reinterpret_cast<uint32_t*>(&h);
}

// ================= kernel 0: W1 fp32 -> bf16 =================
__global__ void prep_w1(const float* __restrict__ W1) {
    const size_t n2 = (size_t)NOUT * F_IN / 2;
    const float2* src = (const float2*)W1;
    uint32_t* dst = (uint32_t*)g_w1b;
    for (size_t i = (size_t)blockIdx.x * blockDim.x + threadIdx.x; i < n2;
         i += (size_t)gridDim.x * blockDim.x) {
        float2 f = src[i];
        dst[i] = p2bf(f.x, f.y);
    }
}

// ================= kernel 1: layer-1 GEMM (mma.sync bf16) =================
// CTA: 512 threads = 16 warps (4 M x 4 N). Warp tile 32(M) x 64(N).
// A fp32 via TMA (SW128), converted to bf16 smem; B bf16 via TMA (SW128).
__global__ void __launch_bounds__(512, 1) nnue_l1(
    const __grid_constant__ CUtensorMap mapA,
    const __grid_constant__ CUtensorMap mapB) {
    extern __shared__ __align__(1024) char smem[];
    const int tid = threadIdx.x;
    const int wid = tid >> 5;
    const int lane = tid & 31;
    const uint32_t sb = su32(smem);
    const int kc = blockIdx.x;           // 0..3 split-K
    const int mt = blockIdx.y;           // 0..31
    const int m0 = mt * MTILE;
    const int kelem0 = kc * NK_PER * KTILE;

    if (tid == 0) {
        mbi(sb + MB_RAWF(0), 1); mbi(sb + MB_RAWF(1), 1);
        mbi(sb + MB_BF(0), 1);   mbi(sb + MB_BF(1), 1);
    }
    __syncthreads();

    // prologue: fill both slots
    if (tid == 0) {
        #pragma unroll
        for (int s = 0; s < 2; ++s) {
            const int kx = kelem0 + s * KTILE;
            mbtx(sb + MB_RAWF(s), 32768);
            tma2d(sb + SM_RAW + s * 32768,         &mapA, kx,      m0, sb + MB_RAWF(s));
            tma2d(sb + SM_RAW + s * 32768 + 16384, &mapA, kx + 32, m0, sb + MB_RAWF(s));
            mbtx(sb + MB_BF(s), 32768);
            tma2d(sb + SM_BB + s * 32768, &mapB, kx, 0, sb + MB_BF(s));
        }
    }

    // ---- per-thread precomputed indices ----
    // conversion: 8192 fp32/stage, 16 per thread: row = tid>>2 (0..127), quarter = tid&3
    const int crow = tid >> 2;
    const int cq = tid & 3;
    const int cbox = cq >> 1;                 // which 16KB TMA box
    const uint32_t chalf = (uint32_t)(cq & 1) * 64;
    const uint32_t kxorc = (uint32_t)(crow & 7) * 16;
    const uint32_t crb = (uint32_t)crow * 128;

    // mma fragment addressing
    const int wm = wid & 3;                   // M warp 0..3
    const int wn = wid >> 2;                  // N warp 0..3
    const int t8 = lane >> 3, r8 = lane & 7;
    uint32_t arow[2], axor[2];
    #pragma unroll
    for (int fm = 0; fm < 2; ++fm) {
        const int rg = wm * 32 + fm * 16 + (t8 & 1) * 8 + r8;
        arow[fm] = (uint32_t)rg * 128;
        axor[fm] = (uint32_t)(rg & 7) * 16;
    }
    const uint32_t kA = (uint32_t)(t8 >> 1) * 16;
    uint32_t brow[4], bxor[4];
    #pragma unroll
    for (int g = 0; g < 4; ++g) {
        const int ng = wn * 64 + g * 16 + (t8 >> 1) * 8 + r8;
        brow[g] = (uint32_t)ng * 128;
        bxor[g] = (uint32_t)(ng & 7) * 16;
    }
    const uint32_t kB = (uint32_t)(t8 & 1) * 16;

    float acc[2][8][4];
    #pragma unroll
    for (int fm = 0; fm < 2; ++fm)
        #pragma unroll
        for (int fn = 0; fn < 8; ++fn)
            #pragma unroll
            for (int j = 0; j < 4; ++j) acc[fm][fn][j] = 0.0f;

    for (int it = 0; it < NK_PER; ++it) {
        const int s = it & 1;
        const int ph = (it >> 1) & 1;
        mbwait(sb + MB_RAWF(s), ph);
        mbwait(sb + MB_BF(s), ph);

        // ---- convert fp32 -> bf16 (all 512 threads) ----
        {
            const char* rbox = smem + SM_RAW + s * 32768 + cbox * 16384;
            char* cb = smem + SM_CVT + s * 16384;
            float4 f[4];
            #pragma unroll
            for (int i = 0; i < 4; ++i)
                f[i] = *(const float4*)(rbox + crb + ((chalf + (uint32_t)i * 16) ^ kxorc));
            uint4 u0, u1;
            u0.x = p2bf(f[0].x, f[0].y); u0.y = p2bf(f[0].z, f[0].w);
            u0.z = p2bf(f[1].x, f[1].y); u0.w = p2bf(f[1].z, f[1].w);
            u1.x = p2bf(f[2].x, f[2].y); u1.y = p2bf(f[2].z, f[2].w);
            u1.z = p2bf(f[3].x, f[3].y); u1.w = p2bf(f[3].z, f[3].w);
            const uint32_t wo = (uint32_t)cq * 32;
            *(uint4*)(cb + crb + (wo ^ kxorc)) = u0;
            *(uint4*)(cb + crb + ((wo + 16) ^ kxorc)) = u1;
        }
        __syncthreads();   // cvt visible; raw[s] fully consumed

        if (tid == 0 && it + 2 < NK_PER) {
            const int kx = kelem0 + (it + 2) * KTILE;
            mbtx(sb + MB_RAWF(s), 32768);
            tma2d(sb + SM_RAW + s * 32768,         &mapA, kx,      m0, sb + MB_RAWF(s));
            tma2d(sb + SM_RAW + s * 32768 + 16384, &mapA, kx + 32, m0, sb + MB_RAWF(s));
        }

        // ---- mma: 4 k-steps x (2 A-frags x 8 B-frags) ----
        {
            const uint32_t cvb = sb + SM_CVT + s * 16384;
            const uint32_t bbb = sb + SM_BB + s * 32768;
            #pragma unroll
            for (int kk = 0; kk < 4; ++kk) {
                const uint32_t kb = (uint32_t)kk * 32;
                uint32_t areg[2][4];
                #pragma unroll
                for (int fm = 0; fm < 2; ++fm)
                    ldsm4(areg[fm], cvb + arow[fm] + ((kb + kA) ^ axor[fm]));
                uint32_t breg[4][4];
                #pragma unroll
                for (int g = 0; g < 4; ++g)
                    ldsm4(breg[g], bbb + brow[g] + ((kb + kB) ^ bxor[g]));
                #pragma unroll
                for (int fm = 0; fm < 2; ++fm)
                    #pragma unroll
                    for (int g = 0; g < 4; ++g) {
                        mma16816(acc[fm][2 * g],     areg[fm], &breg[g][0]);
                        mma16816(acc[fm][2 * g + 1], areg[fm], &breg[g][2]);
                    }
            }
        }
        __syncthreads();   // B[s] and cvt[s] fully consumed

        if (tid == 0 && it + 2 < NK_PER) {
            const int kx = kelem0 + (it + 2) * KTILE;
            mbtx(sb + MB_BF(s), 32768);
            tma2d(sb + SM_BB + s * 32768, &mapB, kx, 0, sb + MB_BF(s));
        }
    }

    // ---- epilogue: regs -> g_part slab ----
    {
        const int r0 = m0 + wm * 32 + (lane >> 2);
        const int c0 = wn * 64 + (lane & 3) * 2;
        #pragma unroll
        for (int fm = 0; fm < 2; ++fm) {
            #pragma unroll
            for (int fn = 0; fn < 8; ++fn) {
                const int row = r0 + fm * 16;
                const int col = c0 + fn * 8;
                float* base = g_part + ((size_t)kc * MROWS + row) * NOUT + col;
                *(float2*)base = make_float2(acc[fm][fn][0], acc[fm][fn][1]);
                *(float2*)(base + 8 * NOUT) = make_float2(acc[fm][fn][2], acc[fm][fn][3]);
            }
        }
    }
}

// ================= kernel 2: tail (reduce + L2..L4) =================
#define TAIL_BPB 16
#define SW2_STRIDE 516
#define TAIL_SMEM_FLOATS (32 * SW2_STRIDE + 544 + 32 + 32 * 33 + 32 + 32 + 32 + 4)

__global__ void __launch_bounds__(256, 1) nnue_tail(
    const float* __restrict__ b1, const float* __restrict__ W2, const float* __restrict__ b2,
    const float* __restrict__ W3, const float* __restrict__ b3,
    const float* __restrict__ W4, const float* __restrict__ b4,
    float* __restrict__ out) {
    extern __shared__ __align__(16) float sm[];
    float* sW2 = sm;                                // 32 x 516
    float* sA  = sW2 + 32 * SW2_STRIDE;             // 544 padded
    float* sh2 = sA + 544;                          // 32
    float* sW3 = sh2 + 32;                          // 32 x 33
    float* sb2 = sW3 + 32 * 33;                     // 32
    float* sb3 = sb2 + 32;                          // 32
    float* sW4 = sb3 + 32;                          // 32

    const int t = threadIdx.x;
    for (int idx = t; idx < 32 * 512; idx += 256)
        sW2[(idx >> 9) * SW2_STRIDE + (idx & 511)] = W2[idx];
    for (int idx = t; idx < 1024; idx += 256)
        sW3[(idx >> 5) * 33 + (idx & 31)] = W3[idx];
    if (t < 32) { sb2[t] = b2[t]; sb3[t] = b3[t]; sW4[t] = W4[t]; }
    __syncthreads();

    const int o = t >> 3;            // 0..31
    const int part = t & 7;          // 0..7
    const float4* w4p = (const float4*)(sW2 + o * SW2_STRIDE + part * 64);
    const float4* a4p = (const float4*)(sA + part * 68);

    for (int bi = 0; bi < TAIL_BPB; ++bi) {
        const int b = blockIdx.x * TAIL_BPB + bi;
        // build concat activations a[512]: split-K reduce + bias + relu
        #pragma unroll
        for (int half = 0; half < 2; ++half) {
            const int e = t + half * 256;
            const int row = 2 * b + (e >> 8);
            const int col = e & 255;
            const size_t base = (size_t)row * NOUT + col;
            float v = b1[col];
            v += g_part[base];
            v += g_part[(size_t)1 * MROWS * NOUT + base];
            v += g_part[(size_t)2 * MROWS * NOUT + base];
            v += g_part[(size_t)3 * MROWS * NOUT + base];
            sA[e + ((e >> 6) << 2)] = fmaxf(v, 0.0f);
        }
        __syncthreads();
        // layer 2: 32 outputs, 8 threads each
        float sum = 0.0f;
        #pragma unroll
        for (int i = 0; i < 16; ++i) {
            float4 w = w4p[i], a = a4p[i];
            sum = fmaf(w.x, a.x, sum); sum = fmaf(w.y, a.y, sum);
            sum = fmaf(w.z, a.z, sum); sum = fmaf(w.w, a.w, sum);
        }
        sum += __shfl_down_sync(0xffffffffu, sum, 4, 8);
        sum += __shfl_down_sync(0xffffffffu, sum, 2, 8);
        sum += __shfl_down_sync(0xffffffffu, sum, 1, 8);
        if (part == 0) sh2[o] = fmaxf(sum + sb2[o], 0.0f);
        __syncthreads();
        // layers 3 + 4 on warp 0
        if (t < 32) {
            float h3 = sb3[t];
            #pragma unroll
            for (int j = 0; j < 32; ++j) h3 = fmaf(sW3[t * 33 + j], sh2[j], h3);
            h3 = fmaxf(h3, 0.0f);
            float v = h3 * sW4[t];
            #pragma unroll
            for (int d = 16; d > 0; d >>= 1) v += __shfl_down_sync(0xffffffffu, v, d);
            if (t == 0) out[b] = 1.0f / (1.0f + expf(-(v + b4[0])));
        }
        __syncthreads();
    }
}

// ================= host =================
typedef CUresult (*EncodeTiledFn)(
    CUtensorMap*, CUtensorMapDataType, cuuint32_t, void*,
    const cuuint64_t*, const cuuint64_t*, const cuuint32_t*, const cuuint32_t*,
    CUtensorMapInterleave, CUtensorMapSwizzle, CUtensorMapL2promotion, CUtensorMapFloatOOBfill);

extern "C" void kernel_launch(void* const* d_in, const int* in_sizes, int n_in,
                              void* d_out, int out_size) {
    const float* x  = (const float*)d_in[0];
    const float* W1 = (const float*)d_in[1];
    const float* b1 = (const float*)d_in[2];
    const float* W2 = (const float*)d_in[3];
    const float* b2 = (const float*)d_in[4];
    const float* W3 = (const float*)d_in[5];
    const float* b3 = (const float*)d_in[6];
    const float* W4 = (const float*)d_in[7];
    const float* b4 = (const float*)d_in[8];
    float* out = (float*)d_out;

    EncodeTiledFn encode = nullptr;
    cudaDriverEntryPointQueryResult qres;
    cudaGetDriverEntryPoint("cuTensorMapEncodeTiled", (void**)&encode,
                            cudaEnableDefault, &qres);

    void* pw1b = nullptr;
    cudaGetSymbolAddress(&pw1b, g_w1b);

    CUtensorMap mapA, mapB;
    {
        cuuint64_t dims[2]    = {(cuuint64_t)F_IN, (cuuint64_t)MROWS};
        cuuint64_t strides[1] = {(cuuint64_t)F_IN * sizeof(float)};
        cuuint32_t box[2]     = {32u, 128u};     // 32 fp32 = 128B (SW128 atom)
        cuuint32_t es[2]      = {1u, 1u};
        encode(&mapA, CU_TENSOR_MAP_DATA_TYPE_FLOAT32, 2, (void*)x,
               dims, strides, box, es,
               CU_TENSOR_MAP_INTERLEAVE_NONE, CU_TENSOR_MAP_SWIZZLE_128B,
               CU_TENSOR_MAP_L2_PROMOTION_L2_128B, CU_TENSOR_MAP_FLOAT_OOB_FILL_NONE);
    }
    {
        cuuint64_t dims[2]    = {(cuuint64_t)F_IN, (cuuint64_t)NOUT};
        cuuint64_t strides[1] = {(cuuint64_t)F_IN * sizeof(__nv_bfloat16)};
        cuuint32_t box[2]     = {64u, 256u};     // 64 bf16 = 128B
        cuuint32_t es[2]      = {1u, 1u};
        encode(&mapB, CU_TENSOR_MAP_DATA_TYPE_BFLOAT16, 2, pw1b,
               dims, strides, box, es,
               CU_TENSOR_MAP_INTERLEAVE_NONE, CU_TENSOR_MAP_SWIZZLE_128B,
               CU_TENSOR_MAP_L2_PROMOTION_L2_128B, CU_TENSOR_MAP_FLOAT_OOB_FILL_NONE);
    }

    cudaFuncSetAttribute(nnue_l1, cudaFuncAttributeMaxDynamicSharedMemorySize, SMEM_SZ);
    cudaFuncSetAttribute(nnue_tail, cudaFuncAttributeMaxDynamicSharedMemorySize,
                         TAIL_SMEM_FLOATS * (int)sizeof(float));

    prep_w1<<<1024, 256>>>(W1);
    dim3 grid(KSPLIT, MROWS / MTILE);            // (4, 32)
    nnue_l1<<<grid, 512, SMEM_SZ>>>(mapA, mapB);
    nnue_tail<<<2048 / TAIL_BPB, 256, TAIL_SMEM_FLOATS * sizeof(float)>>>(
        b1, W2, b2, W3, b3, W4, b4, out);
}